// round 6
// baseline (speedup 1.0000x reference)
#include <cuda_runtime.h>
#include <cuda_fp16.h>
#include <stdint.h>

// Problem shape (fixed by the dataset)
#define B_ 16
#define T_ 51
#define P_ 2048
#define Q_ 2048

// Tiling
#define PC 32                     // p's per slab (== warp size: lane = pl for coalesced loads)
#define NP 2                      // p-chunks accumulated per block
#define PSPLIT (P_ / (PC * NP))   // 32 partial slices
#define QT 256                    // q's per main block (1 per thread)
#define QSPLIT (Q_ / QT)          // 8
#define ROWB 48                   // bytes per (p,t) row: 16 halfs (32B) + 16B pad -> odd granule stride
#define SLAB_B (T_ * ROWB)        // 2448 bytes per p
#define SLAB_TOTAL (PC * SLAB_B)  // 78336 bytes of dynamic smem

#define BQ (B_ * Q_)              // 32768 outputs
#define RSLICE 4                  // reduce stage-A slices
#define RCHUNK (PSPLIT / RSLICE)  // 8 chunks per slice

// Static device scratch (no allocations allowed)
__device__ float g_partial[(size_t)PSPLIT * BQ];    // 4.2 MB
__device__ float g_partial2[(size_t)RSLICE * BQ];   // 0.5 MB

__device__ __forceinline__ __half2 uint_as_half2(unsigned u) {
    __half2 h;
    *reinterpret_cast<unsigned*>(&h) = u;
    return h;
}

// Per-p scalar bundle: delay -> (row index, blended weights)
struct Sc { float wa, w1; int df; };

__device__ __forceinline__ Sc mk_scal(float w, float draw) {
    // d = D_MAX * sigmoid(draw); continuous in d so fast-math floor flips are harmless
    float d   = 50.0f * __fdividef(1.0f, 1.0f + __expf(-draw));
    float fdf = floorf(d);
    int   df  = (int)fdf;
    if (df > 49) { df = 49; fdf = 49.0f; }   // d==50 edge: alpha -> 1, picks row 50
    float a = d - fdf;
    Sc s;
    s.wa = w * a;
    s.w1 = w - s.wa;                          // w * (1 - a)
    s.df = df;
    return s;
}

__device__ __forceinline__ void load_row(uint4* v, const unsigned char* smem, int pl, int df) {
    const unsigned char* row = smem + pl * SLAB_B + df * ROWB;
    v[0] = *reinterpret_cast<const uint4*>(row);                // tap df,   b0..b7
    v[1] = *reinterpret_cast<const uint4*>(row + 16);           // tap df,   b8..b15
    v[2] = *reinterpret_cast<const uint4*>(row + ROWB);         // tap df+1, b0..b7
    v[3] = *reinterpret_cast<const uint4*>(row + ROWB + 16);    // tap df+1, b8..b15
}

__device__ __forceinline__ void consume(const uint4* v, Sc s, float* acc) {
    float wa = s.wa, w1 = s.w1;
#define STEP(uf, uc, i0) {                                          \
        float2 sf = __half22float2(uint_as_half2(uf));              \
        float2 sc = __half22float2(uint_as_half2(uc));              \
        acc[i0]     = fmaf(w1, sf.x, fmaf(wa, sc.x, acc[i0]));      \
        acc[i0 + 1] = fmaf(w1, sf.y, fmaf(wa, sc.y, acc[i0 + 1])); }
    STEP(v[0].x, v[2].x, 0)  STEP(v[0].y, v[2].y, 2)
    STEP(v[0].z, v[2].z, 4)  STEP(v[0].w, v[2].w, 6)
    STEP(v[1].x, v[3].x, 8)  STEP(v[1].y, v[3].y, 10)
    STEP(v[1].z, v[3].z, 12) STEP(v[1].w, v[3].w, 14)
#undef STEP
}

// ---------------------------------------------------------------------------
// Main kernel: for NP p-chunks, build fp16 slab in-block from buf, then a
// software-pipelined gather + weighted-accumulate (double-buffered LDS,
// scalars staged 1-2 p ahead, raw weight/delay prefetched 2-3 p ahead).
// ---------------------------------------------------------------------------
__global__ void __launch_bounds__(256, 2)
main_kernel(const float* __restrict__ buf,
            const float* __restrict__ weight,
            const float* __restrict__ delay) {
    extern __shared__ unsigned char smem[];
    const int qb  = blockIdx.x;           // 0..QSPLIT-1
    const int pb2 = blockIdx.y;           // 0..PSPLIT-1
    const int q   = qb * QT + threadIdx.x;

    float acc[16];
#pragma unroll
    for (int b = 0; b < 16; b++) acc[b] = 0.0f;

    for (int c = 0; c < NP; c++) {
        const int p0 = (pb2 * NP + c) * PC;
        if (c) __syncthreads();           // everyone done reading previous slab

        // ---- Phase 1: build fp16 slab [pl][t][b] directly from buf ----
        // lane = pl -> coalesced 128B LDG per (b,t); STS.128 granule
        // pl*153 + 3t + o -> superbank (pl+3t+o) mod 8 = exact 4-way (floor).
        {
            const int lane = threadIdx.x & 31;
            const int warp = threadIdx.x >> 5;
            for (int item = warp; item < T_ * 2; item += 8) {
                const int t = item >> 1;
                const int o = item & 1;
                const float* src = buf + (size_t)(8 * o) * T_ * P_ + (size_t)t * P_ + p0 + lane;
                unsigned u[4];
#pragma unroll
                for (int k = 0; k < 4; k++) {
                    float lo = src[(size_t)(2 * k)     * T_ * P_];
                    float hi = src[(size_t)(2 * k + 1) * T_ * P_];
                    __half2 hh = __floats2half2_rn(lo, hi);
                    u[k] = *reinterpret_cast<unsigned*>(&hh);
                }
                *reinterpret_cast<uint4*>(smem + lane * SLAB_B + t * ROWB + o * 16) =
                    make_uint4(u[0], u[1], u[2], u[3]);
            }
        }
        __syncthreads();

        // ---- Phase 2: pipelined gather + accumulate ----
        const float* wp = weight + (size_t)p0 * Q_ + q;
        const float* dp = delay  + (size_t)p0 * Q_ + q;

        // Prologue: raws for p+1, p+2 in flight; scalars + row for p=0 ready.
        float wr1 = wp[(size_t)1 * Q_], dr1 = dp[(size_t)1 * Q_];
        float wr2 = wp[(size_t)2 * Q_], dr2 = dp[(size_t)2 * Q_];
        Sc s0 = mk_scal(wp[0], dp[0]);
        uint4 A[4];
        load_row(A, smem, 0, s0.df);

#pragma unroll 2
        for (int pl = 0; pl < PC; pl += 2) {
            // stage pl+1: scalars + loads into B (overlap consume of A)
            Sc s1 = mk_scal(wr1, dr1);
            uint4 Bv[4];
            load_row(Bv, smem, pl + 1, s1.df);

            // stage pl+2 scalars early (MUFU latency hides under consume(A))
            Sc s2 = mk_scal(wr2, dr2);

            // prefetch raws for pl+3 / pl+4 (clamped: valid memory, unused values)
            int i3 = pl + 3 < PC ? pl + 3 : PC - 1;
            int i4 = pl + 4 < PC ? pl + 4 : PC - 1;
            wr1 = wp[(size_t)i3 * Q_]; dr1 = dp[(size_t)i3 * Q_];
            wr2 = wp[(size_t)i4 * Q_]; dr2 = dp[(size_t)i4 * Q_];

            consume(A, s0, acc);

            // stage pl+2 loads into A (overlap consume of B); clamp at tail
            int i2 = pl + 2 < PC ? pl + 2 : PC - 1;
            load_row(A, smem, i2, s2.df);

            consume(Bv, s1, acc);
            s0 = s2;
        }
    }

    // Write fp32 partials for this p-chunk pair (coalesced over q).
    float* part = g_partial + (size_t)pb2 * BQ + q;
#pragma unroll
    for (int b = 0; b < 16; b++) part[(size_t)b * Q_] = acc[b];
}

// ---------------------------------------------------------------------------
// Deterministic two-stage reduction of partials -> out [B, Q]
// ---------------------------------------------------------------------------
__global__ void reduceA_kernel() {
    int i = blockIdx.x * blockDim.x + threadIdx.x;   // 0 .. BQ-1
    const float* src = g_partial + (size_t)(blockIdx.y * RCHUNK) * BQ + i;
    float s = 0.0f;
#pragma unroll
    for (int k = 0; k < RCHUNK; k++) s += src[(size_t)k * BQ];
    g_partial2[(size_t)blockIdx.y * BQ + i] = s;
}

__global__ void reduceB_kernel(float* __restrict__ out) {
    int i = blockIdx.x * blockDim.x + threadIdx.x;   // 0 .. BQ-1
    float s = 0.0f;
#pragma unroll
    for (int c = 0; c < RSLICE; c++) s += g_partial2[(size_t)c * BQ + i];
    out[i] = s;
}

// ---------------------------------------------------------------------------
extern "C" void kernel_launch(void* const* d_in, const int* in_sizes, int n_in,
                              void* d_out, int out_size) {
    (void)in_sizes; (void)n_in; (void)out_size;
    const float* buf    = (const float*)d_in[0];
    const float* weight = (const float*)d_in[1];
    const float* delay  = (const float*)d_in[2];

    cudaFuncSetAttribute(main_kernel, cudaFuncAttributeMaxDynamicSharedMemorySize, SLAB_TOTAL);

    main_kernel<<<dim3(QSPLIT, PSPLIT), QT, SLAB_TOTAL>>>(buf, weight, delay);
    reduceA_kernel<<<dim3(BQ / 128, RSLICE), 128>>>();   // 1024 blocks: spread across all SMs
    reduceB_kernel<<<BQ / 256, 256>>>((float*)d_out);
}

// round 7
// speedup vs baseline: 1.0342x; 1.0342x over previous
#include <cuda_runtime.h>
#include <cuda_fp16.h>
#include <stdint.h>

// Problem shape (fixed by the dataset)
#define B_ 16
#define T_ 51
#define P_ 2048
#define Q_ 2048

// Tiling
#define PC 32                     // p's per slab (== warp size: lane = pl for coalesced loads)
#define PSPLIT (P_ / PC)          // 64 partial slices
#define QT 256                    // q's per main block (1 per thread)
#define QSPLIT (Q_ / QT)          // 8
// Slab layout: per-p region of 105 granules (16B each). Row t occupies
// granules {2t, 2t+1} (b0..7, b8..15), XOR-swizzled: g' = g ^ ((g>>3)&7).
// 105 is odd -> phase-1 STS (lane = pl) spreads all 8 superbanks.
#define PGRAN 105
#define SLAB_B (PGRAN * 16)       // 1680 bytes per p
#define SLAB_TOTAL (PC * SLAB_B)  // 53760 bytes of dynamic smem -> 4 blocks/SM

#define BQ (B_ * Q_)              // 32768 outputs
#define RSLICE 4                  // reduce stage-A slices
#define RCHUNK (PSPLIT / RSLICE)  // 16 chunks per slice

// Static device scratch (no allocations allowed)
__device__ float g_partial[(size_t)PSPLIT * BQ];    // 8.4 MB
__device__ float g_partial2[(size_t)RSLICE * BQ];   // 0.5 MB

__device__ __forceinline__ __half2 uint_as_half2(unsigned u) {
    __half2 h;
    *reinterpret_cast<unsigned*>(&h) = u;
    return h;
}

__device__ __forceinline__ unsigned swz(unsigned g) {   // bijective within 105-granule region
    return g ^ ((g >> 3) & 7u);
}

// ---------------------------------------------------------------------------
// Main kernel: build fp16 slab [pl][t][b] in-block from buf (swizzled),
// then gather + weighted-accumulate. 4 blocks/SM (32 warps) for latency hiding.
// ---------------------------------------------------------------------------
__global__ void __launch_bounds__(256, 4)
main_kernel(const float* __restrict__ buf,
            const float* __restrict__ weight,
            const float* __restrict__ delay) {
    extern __shared__ unsigned char smem[];
    const int qb = blockIdx.x;            // 0..QSPLIT-1
    const int pb = blockIdx.y;            // 0..PSPLIT-1
    const int q  = qb * QT + threadIdx.x;
    const int p0 = pb * PC;

    // ---- Phase 1: build fp16 slab directly from buf ----
    // lane = pl -> coalesced 128B LDG per (b,t). STS.128 at granule
    // lane*105 + swz(2t+o): superbank (lane + swz)&7 -> exact 4-way.
    {
        const int lane = threadIdx.x & 31;
        const int warp = threadIdx.x >> 5;
        for (int item = warp; item < T_ * 2; item += 8) {
            const int t = item >> 1;
            const int o = item & 1;
            const float* src = buf + (size_t)(8 * o) * T_ * P_ + (size_t)t * P_ + p0 + lane;
            unsigned u[4];
#pragma unroll
            for (int k = 0; k < 4; k++) {
                float lo = src[(size_t)(2 * k)     * T_ * P_];
                float hi = src[(size_t)(2 * k + 1) * T_ * P_];
                __half2 hh = __floats2half2_rn(lo, hi);
                u[k] = *reinterpret_cast<unsigned*>(&hh);
            }
            *reinterpret_cast<uint4*>(smem + (lane * PGRAN + swz(2u * t + o)) * 16) =
                make_uint4(u[0], u[1], u[2], u[3]);
        }
    }
    __syncthreads();

    // ---- Phase 2: gather + accumulate ----
    float acc[16];
#pragma unroll
    for (int b = 0; b < 16; b++) acc[b] = 0.0f;

    const float* wp = weight + (size_t)p0 * Q_ + q;
    const float* dp = delay  + (size_t)p0 * Q_ + q;
    float w_n = wp[0];
    float d_n = dp[0];

#pragma unroll 2
    for (int pl = 0; pl < PC; pl++) {
        float w = w_n, draw = d_n;
        if (pl + 1 < PC) {                 // prefetch next p's weight/delay (coalesced)
            w_n = wp[(size_t)(pl + 1) * Q_];
            d_n = dp[(size_t)(pl + 1) * Q_];
        }

        // d = D_MAX * sigmoid(draw); s is continuous in d so fast-math flips are harmless
        float d   = 50.0f * __fdividef(1.0f, 1.0f + __expf(-draw));
        float fdf = floorf(d);
        int   df  = (int)fdf;
        if (df > 49) { df = 49; fdf = 49.0f; }   // d==50 edge: alpha -> 1, picks row 50
        float a  = d - fdf;
        float wa = w * a;
        float w1 = w - wa;                       // w * (1 - a)

        const unsigned char* base = smem + pl * SLAB_B;
        unsigned g = 2u * (unsigned)df;
        // Taps: g+0 = (df, b0..7), g+1 = (df, b8..15), g+2 = (df+1, b0..7), g+3 = (df+1, b8..15)

#define STEP(uf, uc, i0) {                                          \
        float2 sf = __half22float2(uint_as_half2(uf));              \
        float2 sc = __half22float2(uint_as_half2(uc));              \
        acc[i0]     = fmaf(w1, sf.x, fmaf(wa, sc.x, acc[i0]));      \
        acc[i0 + 1] = fmaf(w1, sf.y, fmaf(wa, sc.y, acc[i0 + 1])); }

        {   // b0..7 half: low transient live range (keeps regs <= 64)
            uint4 f0 = *reinterpret_cast<const uint4*>(base + swz(g)     * 16);
            uint4 c0 = *reinterpret_cast<const uint4*>(base + swz(g + 2) * 16);
            STEP(f0.x, c0.x, 0)  STEP(f0.y, c0.y, 2)
            STEP(f0.z, c0.z, 4)  STEP(f0.w, c0.w, 6)
        }
        {   // b8..15 half
            uint4 f1 = *reinterpret_cast<const uint4*>(base + swz(g + 1) * 16);
            uint4 c1 = *reinterpret_cast<const uint4*>(base + swz(g + 3) * 16);
            STEP(f1.x, c1.x, 8)  STEP(f1.y, c1.y, 10)
            STEP(f1.z, c1.z, 12) STEP(f1.w, c1.w, 14)
        }
#undef STEP
    }

    // Write fp32 partials for this p-chunk (coalesced over q).
    float* part = g_partial + (size_t)pb * BQ + q;
#pragma unroll
    for (int b = 0; b < 16; b++) part[(size_t)b * Q_] = acc[b];
}

// ---------------------------------------------------------------------------
// Deterministic two-stage reduction of partials -> out [B, Q]
// ---------------------------------------------------------------------------
__global__ void reduceA_kernel() {
    int i = blockIdx.x * blockDim.x + threadIdx.x;   // 0 .. BQ-1
    const float* src = g_partial + (size_t)(blockIdx.y * RCHUNK) * BQ + i;
    float s = 0.0f;
#pragma unroll
    for (int k = 0; k < RCHUNK; k++) s += src[(size_t)k * BQ];
    g_partial2[(size_t)blockIdx.y * BQ + i] = s;
}

__global__ void reduceB_kernel(float* __restrict__ out) {
    int i = blockIdx.x * blockDim.x + threadIdx.x;   // 0 .. BQ-1
    float s = 0.0f;
#pragma unroll
    for (int c = 0; c < RSLICE; c++) s += g_partial2[(size_t)c * BQ + i];
    out[i] = s;
}

// ---------------------------------------------------------------------------
extern "C" void kernel_launch(void* const* d_in, const int* in_sizes, int n_in,
                              void* d_out, int out_size) {
    (void)in_sizes; (void)n_in; (void)out_size;
    const float* buf    = (const float*)d_in[0];
    const float* weight = (const float*)d_in[1];
    const float* delay  = (const float*)d_in[2];

    cudaFuncSetAttribute(main_kernel, cudaFuncAttributeMaxDynamicSharedMemorySize, SLAB_TOTAL);

    main_kernel<<<dim3(QSPLIT, PSPLIT), QT, SLAB_TOTAL>>>(buf, weight, delay);
    reduceA_kernel<<<dim3(BQ / 128, RSLICE), 128>>>();
    reduceB_kernel<<<BQ / 256, 256>>>((float*)d_out);
}